// round 13
// baseline (speedup 1.0000x reference)
#include <cuda_runtime.h>
#include <cuda_fp16.h>
#include <cstdint>

#define TKN 8192
#define DM  1024
#define DH  4096
#define DO  1024
#define NE  8
#define RTOT (TKN * 2)
#define RPAD (RTOT + NE * 128)
#define NTMAX (RTOT / 128 + NE)

// dynamic smem layout (per CTA):
//   [0,512)      s_tok (128 int)
//   [512,1024)   s_w   (128 float)
//   [1024, +3*36864)  three stages; each stage = As 128x72 half (18432B) + Bs 128x72 half
#define STAGE_BYTES 36864
#define NSTAGE 3
#define SMEM_BYTES  (1024 + NSTAGE * STAGE_BYTES)

#define NX  (TKN * DM)
#define NW1 (NE * DH * DM)
#define NW2 (NE * DO * DH)

// ---------------- device scratch ----------------
__device__ __half g_xh[TKN * DM];
__device__ __half g_w1h[NE * DH * DM];
__device__ __half g_w2h[NE * DO * DH];
__device__ __half g_h[(size_t)RPAD * DH];
__device__ int    g_bucket[RPAD];
__device__ float  g_bw[RPAD];
__device__ int    g_te[TKN * 2];
__device__ float  g_tw[TKN * 2];
__device__ int    g_counts[NE];
__device__ float  g_psum[NE];
__device__ int    g_fill[NE];
__device__ int    g_tile_e[NTMAX];
__device__ int    g_tile_m[NTMAX];
__device__ int    g_ntiles;

// ---------------- small kernels ----------------
__global__ void k_reset() {
    int i = blockIdx.x * blockDim.x + threadIdx.x;
    if (i < RPAD) g_bucket[i] = -1;
    if (i < NE) { g_counts[i] = 0; g_psum[i] = 0.0f; }
}

// zero the token-output region of out (GEMM2 accumulates into it atomically)
__global__ void k_zero(float* __restrict__ out) {
    int i = (blockIdx.x * blockDim.x + threadIdx.x) * 4;
    if (i < TKN * DO) *(float4*)(out + i) = make_float4(0.f, 0.f, 0.f, 0.f);
}

__device__ __forceinline__ uint32_t h2_bits(__half2 h) {
    uint32_t u;
    *(__half2*)&u = h;
    return u;
}

__device__ __forceinline__ void conv8(const float* __restrict__ s, __half* __restrict__ d, int i) {
    float4 v0 = *(const float4*)(s + i);
    float4 v1 = *(const float4*)(s + i + 4);
    uint4 o;
    o.x = h2_bits(__floats2half2_rn(v0.x, v0.y));
    o.y = h2_bits(__floats2half2_rn(v0.z, v0.w));
    o.z = h2_bits(__floats2half2_rn(v1.x, v1.y));
    o.w = h2_bits(__floats2half2_rn(v1.z, v1.w));
    *(uint4*)(d + i) = o;
}

// single fused fp32->fp16 convert over x, w1, w2
__global__ void k_conv_all(const float* __restrict__ x, const float* __restrict__ w1,
                           const float* __restrict__ w2) {
    const int total = (NX + NW1 + NW2) / 8;
    int t = blockIdx.x * blockDim.x + threadIdx.x;
    int stride = gridDim.x * blockDim.x;
    for (; t < total; t += stride) {
        int i = t * 8;
        if (i < NX) {
            conv8(x, g_xh, i);
        } else if (i < NX + NW1) {
            conv8(w1, g_w1h, i - NX);
        } else {
            conv8(w2, g_w2h, i - NX - NW1);
        }
    }
}

__global__ void k_router(const float* __restrict__ x, const float* __restrict__ rw,
                         const float* __restrict__ rb) {
    int warp = (blockIdx.x * blockDim.x + threadIdx.x) >> 5;
    int lane = threadIdx.x & 31;
    if (warp >= TKN) return;
    const float* xr = x + (size_t)warp * DM;
    float acc[NE];
#pragma unroll
    for (int e = 0; e < NE; e++) acc[e] = 0.0f;
    for (int i = lane; i < DM; i += 32) {
        float xv = xr[i];
#pragma unroll
        for (int e = 0; e < NE; e++) acc[e] += xv * rw[e * DM + i];
    }
#pragma unroll
    for (int off = 16; off; off >>= 1)
#pragma unroll
        for (int e = 0; e < NE; e++) acc[e] += __shfl_xor_sync(0xffffffffu, acc[e], off);

    float lg[NE];
    float mx = -1e30f;
#pragma unroll
    for (int e = 0; e < NE; e++) { lg[e] = acc[e] + rb[e]; mx = fmaxf(mx, lg[e]); }
    float sum = 0.0f;
#pragma unroll
    for (int e = 0; e < NE; e++) { lg[e] = expf(lg[e] - mx); sum += lg[e]; }
    float inv = 1.0f / sum;

    int e0 = 0; float p0 = lg[0];
#pragma unroll
    for (int e = 1; e < NE; e++) if (lg[e] > p0) { p0 = lg[e]; e0 = e; }
    int e1 = -1; float p1 = -1.0f;
#pragma unroll
    for (int e = 0; e < NE; e++) if (e != e0 && lg[e] > p1) { p1 = lg[e]; e1 = e; }
    float wsum = p0 + p1;

    if (lane == 0) {
        g_te[2 * warp] = e0; g_te[2 * warp + 1] = e1;
        g_tw[2 * warp] = p0 / wsum; g_tw[2 * warp + 1] = p1 / wsum;
        atomicAdd(&g_counts[e0], 1);
        atomicAdd(&g_counts[e1], 1);
    }
    if (lane < NE) atomicAdd(&g_psum[lane], lg[lane] * inv);
}

__global__ void k_build() {
    if (threadIdx.x == 0) {
        int off = 0, nt = 0;
        for (int e = 0; e < NE; e++) {
            g_fill[e] = off;
            int c = g_counts[e];
            int tiles = (c + 127) >> 7;
            for (int j = 0; j < tiles; j++) { g_tile_e[nt] = e; g_tile_m[nt] = off + j * 128; nt++; }
            off += tiles * 128;
        }
        g_ntiles = nt;
    }
}

__global__ void k_scatter() {
    int t = blockIdx.x * blockDim.x + threadIdx.x;
    if (t >= TKN) return;
#pragma unroll
    for (int k = 0; k < 2; k++) {
        int e = g_te[2 * t + k];
        int pos = atomicAdd(&g_fill[e], 1);
        g_bucket[pos] = t * 2 + k;
        g_bw[pos] = g_tw[2 * t + k];
    }
}

// ---------------- mma helpers ----------------
__device__ __forceinline__ void ldsm4(uint32_t* r, const void* p) {
    uint32_t addr = (uint32_t)__cvta_generic_to_shared(p);
    asm volatile("ldmatrix.sync.aligned.m8n8.x4.shared.b16 {%0,%1,%2,%3}, [%4];\n"
                 : "=r"(r[0]), "=r"(r[1]), "=r"(r[2]), "=r"(r[3]) : "r"(addr));
}

__device__ __forceinline__ void mma_16816(float* c, const uint32_t* a, const uint32_t* b) {
    asm volatile(
        "mma.sync.aligned.m16n8k16.row.col.f32.f16.f16.f32 "
        "{%0,%1,%2,%3}, {%4,%5,%6,%7}, {%8,%9}, {%0,%1,%2,%3};\n"
        : "+f"(c[0]), "+f"(c[1]), "+f"(c[2]), "+f"(c[3])
        : "r"(a[0]), "r"(a[1]), "r"(a[2]), "r"(a[3]), "r"(b[0]), "r"(b[1]));
}

__device__ __forceinline__ void cpa16(uint32_t dst, const void* src, uint32_t srcsize) {
    asm volatile("cp.async.cg.shared.global [%0], [%1], 16, %2;\n"
                 :: "r"(dst), "l"(src), "r"(srcsize));
}

// ---------------- grouped GEMM: 128x128 tile, BK=64, cp.async 3-stage pipeline -----------
// 8 warps (2x4), warp tile 64x32. Mainloop identical to the validated R11 kernel.
// FIRST=false epilogue accumulates directly into the final output via atomicAdd
// (exactly two contributions per element -> bit-deterministic).
template <int KTOT, bool FIRST>
__global__ __launch_bounds__(256, 2) void k_gemm(const float* __restrict__ bias,
                                                 float* __restrict__ yout) {
    int t = blockIdx.y;
    if (t >= g_ntiles) return;
    const int e = g_tile_e[t];
    const int mbase = g_tile_m[t];
    const int n0 = blockIdx.x * 128;

    extern __shared__ char sm[];
    int*   s_tok = (int*)sm;
    float* s_w   = (float*)(sm + 512);
    const uint32_t smem_u32 = (uint32_t)__cvta_generic_to_shared(sm);

    const int tid = threadIdx.x;
    const int lane = tid & 31;
    const int wid = tid >> 5;
    const int wm = wid >> 2;   // 0..1
    const int wn = wid & 3;    // 0..3

    if (tid < 128) {
        s_tok[tid] = g_bucket[mbase + tid];
        s_w[tid]   = g_bw[mbase + tid];
    }
    __syncthreads();

    const __half* Bbase =
        (FIRST ? g_w1h + (size_t)e * DH * DM : g_w2h + (size_t)e * DO * DH) + (size_t)n0 * KTOT;

    // loader mapping: thread -> (row tr + 32p, half-col tc), 16B per cp.async
    const int tr = tid >> 3;        // 0..31
    const int tc = (tid & 7) << 3;  // 0..56 step 8 halves

    const __half* aptr[4];
    uint32_t asz[4];
    const __half* bptr[4];
#pragma unroll
    for (int p = 0; p < 4; p++) {
        const int rr = tr + 32 * p;
        if (FIRST) {
            int b = s_tok[rr];
            if (b >= 0) { aptr[p] = g_xh + (size_t)(b >> 1) * DM + tc; asz[p] = 16; }
            else        { aptr[p] = g_xh; asz[p] = 0; }
        } else {
            aptr[p] = g_h + (size_t)(mbase + rr) * DH + tc;
            asz[p] = 16;
        }
        bptr[p] = Bbase + (size_t)rr * KTOT + tc;
    }
    const uint32_t dA = smem_u32 + 1024 + (uint32_t)tr * 144 + (uint32_t)tc * 2;
    const uint32_t dB = dA + 18432;

    auto issue = [&](int chunk, int st) {
        const uint32_t so = (uint32_t)st * STAGE_BYTES;
        const int ko = chunk * 64;
#pragma unroll
        for (int p = 0; p < 4; p++) {
            cpa16(dA + so + p * (32 * 144), aptr[p] + ko, asz[p]);
            cpa16(dB + so + p * (32 * 144), bptr[p] + ko, 16u);
        }
        asm volatile("cp.async.commit_group;" ::: "memory");
    };

    float c[4][4][4];
#pragma unroll
    for (int i = 0; i < 4; i++)
#pragma unroll
        for (int j = 0; j < 4; j++)
#pragma unroll
            for (int q = 0; q < 4; q++) c[i][j][q] = 0.0f;

    constexpr int NC = KTOT / 64;
    issue(0, 0);
    issue(1, 1);
    issue(2, 2);

    int st = 0;
    for (int ch = 0; ch < NC; ch++) {
        const int rem = NC - 1 - ch;
        if (rem >= 2)      asm volatile("cp.async.wait_group 2;" ::: "memory");
        else if (rem == 1) asm volatile("cp.async.wait_group 1;" ::: "memory");
        else               asm volatile("cp.async.wait_group 0;" ::: "memory");
        __syncthreads();

        __half (*As)[72] = (__half(*)[72])(sm + 1024 + st * STAGE_BYTES);
        __half (*Bs)[72] = (__half(*)[72])(sm + 1024 + st * STAGE_BYTES + 18432);

#pragma unroll
        for (int kk = 0; kk < 64; kk += 16) {
            uint32_t a[4][4];
#pragma unroll
            for (int i = 0; i < 4; i++) {
                int row = wm * 64 + i * 16 + (lane & 15);
                int col = kk + ((lane >> 4) << 3);
                ldsm4(a[i], &As[row][col]);
            }
            uint32_t b[4][2];
#pragma unroll
            for (int j2 = 0; j2 < 2; j2++) {
                int q = lane >> 3;
                int row = wn * 32 + j2 * 16 + ((q & 2) ? 8 : 0) + (lane & 7);
                int col = kk + ((q & 1) ? 8 : 0);
                uint32_t r4[4];
                ldsm4(r4, &Bs[row][col]);
                b[2 * j2][0] = r4[0]; b[2 * j2][1] = r4[1];
                b[2 * j2 + 1][0] = r4[2]; b[2 * j2 + 1][1] = r4[3];
            }
#pragma unroll
            for (int i = 0; i < 4; i++)
#pragma unroll
                for (int j = 0; j < 4; j++) mma_16816(c[i][j], a[i], b[j]);
        }
        __syncthreads();
        if (ch + NSTAGE < NC) issue(ch + NSTAGE, st);
        st = (st == NSTAGE - 1) ? 0 : st + 1;
    }

    // epilogue
    const float* brow = bias + (size_t)e * (FIRST ? DH : DO) + n0;
#pragma unroll
    for (int i = 0; i < 4; i++) {
        int r = wm * 64 + i * 16 + (lane >> 2);
#pragma unroll
        for (int j = 0; j < 4; j++) {
            int cn = wn * 32 + j * 8 + ((lane & 3) << 1);
            float b0 = brow[cn], b1 = brow[cn + 1];
            if (FIRST) {
                float v0 = fmaxf(c[i][j][0] + b0, 0.0f);
                float v1 = fmaxf(c[i][j][1] + b1, 0.0f);
                *(__half2*)(&g_h[(size_t)(mbase + r) * DH + n0 + cn]) = __floats2half2_rn(v0, v1);
                float v2 = fmaxf(c[i][j][2] + b0, 0.0f);
                float v3 = fmaxf(c[i][j][3] + b1, 0.0f);
                *(__half2*)(&g_h[(size_t)(mbase + r + 8) * DH + n0 + cn]) = __floats2half2_rn(v2, v3);
            } else {
                int v = s_tok[r];
                if (v >= 0) {
                    float wgt = s_w[r];
                    float* orow = yout + (size_t)(v >> 1) * DO + n0 + cn;
                    atomicAdd(orow,     wgt * (c[i][j][0] + b0));
                    atomicAdd(orow + 1, wgt * (c[i][j][1] + b1));
                }
                int v2 = s_tok[r + 8];
                if (v2 >= 0) {
                    float wgt = s_w[r + 8];
                    float* orow = yout + (size_t)(v2 >> 1) * DO + n0 + cn;
                    atomicAdd(orow,     wgt * (c[i][j][2] + b0));
                    atomicAdd(orow + 1, wgt * (c[i][j][3] + b1));
                }
            }
        }
    }
}

__global__ void k_final(float* __restrict__ out, int out_size) {
    if (threadIdx.x == 0 && blockIdx.x == 0) {
        float lb = 0.0f;
        for (int e = 0; e < NE; e++)
            lb += ((float)g_counts[e] / (float)(TKN * 2)) * (g_psum[e] / (float)TKN);
        out[out_size - 1] = 0.01f * (float)NE * lb;
    }
}

// ---------------- launch ----------------
extern "C" void kernel_launch(void* const* d_in, const int* in_sizes, int n_in,
                              void* d_out, int out_size) {
    const float* x  = (const float*)d_in[0];
    const float* rw = (const float*)d_in[1];
    const float* rb = (const float*)d_in[2];
    const float* w1 = (const float*)d_in[3];
    const float* b1 = (const float*)d_in[4];
    const float* w2 = (const float*)d_in[5];
    const float* b2 = (const float*)d_in[6];
    float* out = (float*)d_out;
    (void)in_sizes; (void)n_in;

    cudaFuncSetAttribute(k_gemm<DM, true>,
                         cudaFuncAttributeMaxDynamicSharedMemorySize, SMEM_BYTES);
    cudaFuncSetAttribute(k_gemm<DH, false>,
                         cudaFuncAttributeMaxDynamicSharedMemorySize, SMEM_BYTES);

    k_reset<<<(RPAD + 255) / 256, 256>>>();
    k_zero<<<(TKN * DO / 4 + 255) / 256, 256>>>(out);
    k_conv_all<<<8192, 256>>>(x, w1, w2);
    k_router<<<(TKN * 32) / 256, 256>>>(x, rw, rb);
    k_build<<<1, 32>>>();
    k_scatter<<<(TKN + 255) / 256, 256>>>();

    dim3 g1(DH / 128, NTMAX);
    k_gemm<DM, true><<<g1, 256, SMEM_BYTES>>>(b1, nullptr);
    dim3 g2(DO / 128, NTMAX);
    k_gemm<DH, false><<<g2, 256, SMEM_BYTES>>>(b2, out);

    k_final<<<1, 32>>>(out, out_size);
}

// round 14
// speedup vs baseline: 1.4677x; 1.4677x over previous
#include <cuda_runtime.h>
#include <cuda_fp16.h>
#include <cstdint>

#define TKN 8192
#define DM  1024
#define DH  4096
#define DO  1024
#define NE  8
#define RTOT (TKN * 2)
#define RPAD (RTOT + NE * 128)
#define NTMAX (RTOT / 128 + NE)

// dynamic smem layout (per CTA):
//   [0,512)      s_tok (128 int)
//   [512,1024)   s_w   (128 float)
//   [1024, +3*36864)  three stages; each stage = As 128x72 half (18432B) + Bs 128x72 half
#define STAGE_BYTES 36864
#define NSTAGE 3
#define SMEM_BYTES  (1024 + NSTAGE * STAGE_BYTES)

// ---------------- device scratch ----------------
__device__ __half g_xh[TKN * DM];
__device__ __half g_w1h[NE * DH * DM];
__device__ __half g_w2h[NE * DO * DH];
__device__ __half g_h[(size_t)RPAD * DH];
__device__ float  g_y[(size_t)RTOT * DO];
__device__ int    g_bucket[RPAD];
__device__ float  g_bw[RPAD];
__device__ int    g_te[TKN * 2];
__device__ float  g_tw[TKN * 2];
__device__ int    g_counts[NE];
__device__ float  g_psum[NE];
__device__ int    g_fill[NE];
__device__ int    g_tile_e[NTMAX];
__device__ int    g_tile_m[NTMAX];
__device__ int    g_ntiles;

// ---------------- small kernels ----------------
__global__ void k_reset() {
    int i = blockIdx.x * blockDim.x + threadIdx.x;
    if (i < RPAD) g_bucket[i] = -1;
    if (i < NE) { g_counts[i] = 0; g_psum[i] = 0.0f; }
}

__device__ __forceinline__ uint32_t h2_bits(__half2 h) {
    uint32_t u;
    *(__half2*)&u = h;
    return u;
}

// 8 floats per thread-iter: 2x float4 load, 1x uint4 (16B) store
__global__ void k_conv(const float* __restrict__ src, __half* __restrict__ dst, int n) {
    int i = (blockIdx.x * blockDim.x + threadIdx.x) * 8;
    int stride = gridDim.x * blockDim.x * 8;
    for (; i < n; i += stride) {
        float4 v0 = *(const float4*)(src + i);
        float4 v1 = *(const float4*)(src + i + 4);
        uint4 o;
        o.x = h2_bits(__floats2half2_rn(v0.x, v0.y));
        o.y = h2_bits(__floats2half2_rn(v0.z, v0.w));
        o.z = h2_bits(__floats2half2_rn(v1.x, v1.y));
        o.w = h2_bits(__floats2half2_rn(v1.z, v1.w));
        *(uint4*)(dst + i) = o;
    }
}

// one warp per token; float4-vectorized loads (8 iters x (1 x-load + 8 w-loads))
__global__ void k_router(const float* __restrict__ x, const float* __restrict__ rw,
                         const float* __restrict__ rb) {
    int warp = (blockIdx.x * blockDim.x + threadIdx.x) >> 5;
    int lane = threadIdx.x & 31;
    if (warp >= TKN) return;
    const float* xr = x + (size_t)warp * DM;
    float acc[NE];
#pragma unroll
    for (int e = 0; e < NE; e++) acc[e] = 0.0f;
#pragma unroll
    for (int j = 0; j < 8; j++) {
        int i = j * 128 + lane * 4;
        float4 xv = *(const float4*)(xr + i);
#pragma unroll
        for (int e = 0; e < NE; e++) {
            float4 wv = *(const float4*)(rw + e * DM + i);
            acc[e] += xv.x * wv.x + xv.y * wv.y + xv.z * wv.z + xv.w * wv.w;
        }
    }
#pragma unroll
    for (int off = 16; off; off >>= 1)
#pragma unroll
        for (int e = 0; e < NE; e++) acc[e] += __shfl_xor_sync(0xffffffffu, acc[e], off);

    float lg[NE];
    float mx = -1e30f;
#pragma unroll
    for (int e = 0; e < NE; e++) { lg[e] = acc[e] + rb[e]; mx = fmaxf(mx, lg[e]); }
    float sum = 0.0f;
#pragma unroll
    for (int e = 0; e < NE; e++) { lg[e] = expf(lg[e] - mx); sum += lg[e]; }
    float inv = 1.0f / sum;

    int e0 = 0; float p0 = lg[0];
#pragma unroll
    for (int e = 1; e < NE; e++) if (lg[e] > p0) { p0 = lg[e]; e0 = e; }
    int e1 = -1; float p1 = -1.0f;
#pragma unroll
    for (int e = 0; e < NE; e++) if (e != e0 && lg[e] > p1) { p1 = lg[e]; e1 = e; }
    float wsum = p0 + p1;

    if (lane == 0) {
        g_te[2 * warp] = e0; g_te[2 * warp + 1] = e1;
        g_tw[2 * warp] = p0 / wsum; g_tw[2 * warp + 1] = p1 / wsum;
        atomicAdd(&g_counts[e0], 1);
        atomicAdd(&g_counts[e1], 1);
    }
    if (lane < NE) atomicAdd(&g_psum[lane], lg[lane] * inv);
}

__global__ void k_build() {
    if (threadIdx.x == 0) {
        int off = 0, nt = 0;
        for (int e = 0; e < NE; e++) {
            g_fill[e] = off;
            int c = g_counts[e];
            int tiles = (c + 127) >> 7;
            for (int j = 0; j < tiles; j++) { g_tile_e[nt] = e; g_tile_m[nt] = off + j * 128; nt++; }
            off += tiles * 128;
        }
        g_ntiles = nt;
    }
}

__global__ void k_scatter() {
    int t = blockIdx.x * blockDim.x + threadIdx.x;
    if (t >= TKN) return;
#pragma unroll
    for (int k = 0; k < 2; k++) {
        int e = g_te[2 * t + k];
        int pos = atomicAdd(&g_fill[e], 1);
        g_bucket[pos] = t * 2 + k;
        g_bw[pos] = g_tw[2 * t + k];
    }
}

// ---------------- mma helpers ----------------
__device__ __forceinline__ void ldsm4(uint32_t* r, const void* p) {
    uint32_t addr = (uint32_t)__cvta_generic_to_shared(p);
    asm volatile("ldmatrix.sync.aligned.m8n8.x4.shared.b16 {%0,%1,%2,%3}, [%4];\n"
                 : "=r"(r[0]), "=r"(r[1]), "=r"(r[2]), "=r"(r[3]) : "r"(addr));
}

__device__ __forceinline__ void mma_16816(float* c, const uint32_t* a, const uint32_t* b) {
    asm volatile(
        "mma.sync.aligned.m16n8k16.row.col.f32.f16.f16.f32 "
        "{%0,%1,%2,%3}, {%4,%5,%6,%7}, {%8,%9}, {%0,%1,%2,%3};\n"
        : "+f"(c[0]), "+f"(c[1]), "+f"(c[2]), "+f"(c[3])
        : "r"(a[0]), "r"(a[1]), "r"(a[2]), "r"(a[3]), "r"(b[0]), "r"(b[1]));
}

__device__ __forceinline__ void cpa16(uint32_t dst, const void* src, uint32_t srcsize) {
    asm volatile("cp.async.cg.shared.global [%0], [%1], 16, %2;\n"
                 :: "r"(dst), "l"(src), "r"(srcsize));
}

// ---------------- grouped GEMM: 128x128 tile, BK=64, cp.async 3-stage pipeline -----------
// 8 warps (2x4), warp tile 64x32. Identical to the validated R11 kernel.
template <int KTOT, bool FIRST>
__global__ __launch_bounds__(256, 2) void k_gemm(const float* __restrict__ bias) {
    int t = blockIdx.y;
    if (t >= g_ntiles) return;
    const int e = g_tile_e[t];
    const int mbase = g_tile_m[t];
    const int n0 = blockIdx.x * 128;

    extern __shared__ char sm[];
    int*   s_tok = (int*)sm;
    float* s_w   = (float*)(sm + 512);
    const uint32_t smem_u32 = (uint32_t)__cvta_generic_to_shared(sm);

    const int tid = threadIdx.x;
    const int lane = tid & 31;
    const int wid = tid >> 5;
    const int wm = wid >> 2;   // 0..1
    const int wn = wid & 3;    // 0..3

    if (tid < 128) {
        s_tok[tid] = g_bucket[mbase + tid];
        s_w[tid]   = g_bw[mbase + tid];
    }
    __syncthreads();

    const __half* Bbase =
        (FIRST ? g_w1h + (size_t)e * DH * DM : g_w2h + (size_t)e * DO * DH) + (size_t)n0 * KTOT;

    // loader mapping: thread -> (row tr + 32p, half-col tc), 16B per cp.async
    const int tr = tid >> 3;        // 0..31
    const int tc = (tid & 7) << 3;  // 0..56 step 8 halves

    const __half* aptr[4];
    uint32_t asz[4];
    const __half* bptr[4];
#pragma unroll
    for (int p = 0; p < 4; p++) {
        const int rr = tr + 32 * p;
        if (FIRST) {
            int b = s_tok[rr];
            if (b >= 0) { aptr[p] = g_xh + (size_t)(b >> 1) * DM + tc; asz[p] = 16; }
            else        { aptr[p] = g_xh; asz[p] = 0; }
        } else {
            aptr[p] = g_h + (size_t)(mbase + rr) * DH + tc;
            asz[p] = 16;
        }
        bptr[p] = Bbase + (size_t)rr * KTOT + tc;
    }
    const uint32_t dA = smem_u32 + 1024 + (uint32_t)tr * 144 + (uint32_t)tc * 2;
    const uint32_t dB = dA + 18432;

    auto issue = [&](int chunk, int st) {
        const uint32_t so = (uint32_t)st * STAGE_BYTES;
        const int ko = chunk * 64;
#pragma unroll
        for (int p = 0; p < 4; p++) {
            cpa16(dA + so + p * (32 * 144), aptr[p] + ko, asz[p]);
            cpa16(dB + so + p * (32 * 144), bptr[p] + ko, 16u);
        }
        asm volatile("cp.async.commit_group;" ::: "memory");
    };

    float c[4][4][4];
#pragma unroll
    for (int i = 0; i < 4; i++)
#pragma unroll
        for (int j = 0; j < 4; j++)
#pragma unroll
            for (int q = 0; q < 4; q++) c[i][j][q] = 0.0f;

    constexpr int NC = KTOT / 64;
    issue(0, 0);
    issue(1, 1);
    issue(2, 2);

    int st = 0;
    for (int ch = 0; ch < NC; ch++) {
        const int rem = NC - 1 - ch;
        if (rem >= 2)      asm volatile("cp.async.wait_group 2;" ::: "memory");
        else if (rem == 1) asm volatile("cp.async.wait_group 1;" ::: "memory");
        else               asm volatile("cp.async.wait_group 0;" ::: "memory");
        __syncthreads();

        __half (*As)[72] = (__half(*)[72])(sm + 1024 + st * STAGE_BYTES);
        __half (*Bs)[72] = (__half(*)[72])(sm + 1024 + st * STAGE_BYTES + 18432);

#pragma unroll
        for (int kk = 0; kk < 64; kk += 16) {
            uint32_t a[4][4];
#pragma unroll
            for (int i = 0; i < 4; i++) {
                int row = wm * 64 + i * 16 + (lane & 15);
                int col = kk + ((lane >> 4) << 3);
                ldsm4(a[i], &As[row][col]);
            }
            uint32_t b[4][2];
#pragma unroll
            for (int j2 = 0; j2 < 2; j2++) {
                int q = lane >> 3;
                int row = wn * 32 + j2 * 16 + ((q & 2) ? 8 : 0) + (lane & 7);
                int col = kk + ((q & 1) ? 8 : 0);
                uint32_t r4[4];
                ldsm4(r4, &Bs[row][col]);
                b[2 * j2][0] = r4[0]; b[2 * j2][1] = r4[1];
                b[2 * j2 + 1][0] = r4[2]; b[2 * j2 + 1][1] = r4[3];
            }
#pragma unroll
            for (int i = 0; i < 4; i++)
#pragma unroll
                for (int j = 0; j < 4; j++) mma_16816(c[i][j], a[i], b[j]);
        }
        __syncthreads();
        if (ch + NSTAGE < NC) issue(ch + NSTAGE, st);
        st = (st == NSTAGE - 1) ? 0 : st + 1;
    }

    // epilogue (identical to R1/R11)
    const float* brow = bias + (size_t)e * (FIRST ? DH : DO) + n0;
#pragma unroll
    for (int i = 0; i < 4; i++) {
        int r = wm * 64 + i * 16 + (lane >> 2);
#pragma unroll
        for (int j = 0; j < 4; j++) {
            int cn = wn * 32 + j * 8 + ((lane & 3) << 1);
            float b0 = brow[cn], b1 = brow[cn + 1];
            if (FIRST) {
                float v0 = fmaxf(c[i][j][0] + b0, 0.0f);
                float v1 = fmaxf(c[i][j][1] + b1, 0.0f);
                *(__half2*)(&g_h[(size_t)(mbase + r) * DH + n0 + cn]) = __floats2half2_rn(v0, v1);
                float v2 = fmaxf(c[i][j][2] + b0, 0.0f);
                float v3 = fmaxf(c[i][j][3] + b1, 0.0f);
                *(__half2*)(&g_h[(size_t)(mbase + r + 8) * DH + n0 + cn]) = __floats2half2_rn(v2, v3);
            } else {
                int v = s_tok[r];
                if (v >= 0) {
                    float wgt = s_w[r];
                    float2 o;
                    o.x = wgt * (c[i][j][0] + b0);
                    o.y = wgt * (c[i][j][1] + b1);
                    *(float2*)(&g_y[(size_t)v * DO + n0 + cn]) = o;
                }
                int v2 = s_tok[r + 8];
                if (v2 >= 0) {
                    float wgt = s_w[r + 8];
                    float2 o;
                    o.x = wgt * (c[i][j][2] + b0);
                    o.y = wgt * (c[i][j][3] + b1);
                    *(float2*)(&g_y[(size_t)v2 * DO + n0 + cn]) = o;
                }
            }
        }
    }
}

__global__ void k_combine(float* __restrict__ out, int out_size) {
    int i = blockIdx.x * blockDim.x + threadIdx.x;
    if (i >= out_size) return;
    if (i < TKN * DO) {
        int t = i >> 10;
        int cc = i & 1023;
        out[i] = g_y[(size_t)(t * 2) * DO + cc] + g_y[(size_t)(t * 2 + 1) * DO + cc];
    } else {
        out[i] = 0.0f;
    }
}

__global__ void k_final(float* __restrict__ out, int out_size) {
    if (threadIdx.x == 0 && blockIdx.x == 0) {
        float lb = 0.0f;
        for (int e = 0; e < NE; e++)
            lb += ((float)g_counts[e] / (float)(TKN * 2)) * (g_psum[e] / (float)TKN);
        out[out_size - 1] = 0.01f * (float)NE * lb;
    }
}

// ---------------- launch ----------------
extern "C" void kernel_launch(void* const* d_in, const int* in_sizes, int n_in,
                              void* d_out, int out_size) {
    const float* x  = (const float*)d_in[0];
    const float* rw = (const float*)d_in[1];
    const float* rb = (const float*)d_in[2];
    const float* w1 = (const float*)d_in[3];
    const float* b1 = (const float*)d_in[4];
    const float* w2 = (const float*)d_in[5];
    const float* b2 = (const float*)d_in[6];
    float* out = (float*)d_out;
    (void)in_sizes; (void)n_in;

    __half* xh;  cudaGetSymbolAddress((void**)&xh,  g_xh);
    __half* w1h; cudaGetSymbolAddress((void**)&w1h, g_w1h);
    __half* w2h; cudaGetSymbolAddress((void**)&w2h, g_w2h);

    cudaFuncSetAttribute(k_gemm<DM, true>,
                         cudaFuncAttributeMaxDynamicSharedMemorySize, SMEM_BYTES);
    cudaFuncSetAttribute(k_gemm<DH, false>,
                         cudaFuncAttributeMaxDynamicSharedMemorySize, SMEM_BYTES);

    k_reset<<<(RPAD + 255) / 256, 256>>>();
    k_conv<<<1024, 256>>>(x,  xh,  TKN * DM);
    k_conv<<<4096, 256>>>(w1, w1h, NE * DH * DM);
    k_conv<<<4096, 256>>>(w2, w2h, NE * DO * DH);
    k_router<<<(TKN * 32) / 256, 256>>>(x, rw, rb);
    k_build<<<1, 32>>>();
    k_scatter<<<(TKN + 255) / 256, 256>>>();

    dim3 g1(DH / 128, NTMAX);
    k_gemm<DM, true><<<g1, 256, SMEM_BYTES>>>(b1);
    dim3 g2(DO / 128, NTMAX);
    k_gemm<DH, false><<<g2, 256, SMEM_BYTES>>>(b2);

    k_combine<<<(out_size + 255) / 256, 256>>>(out, out_size);
    k_final<<<1, 32>>>(out, out_size);
}

// round 15
// speedup vs baseline: 1.5027x; 1.0238x over previous
#include <cuda_runtime.h>
#include <cuda_fp16.h>
#include <cstdint>

#define TKN 8192
#define DM  1024
#define DH  4096
#define DO  1024
#define NE  8
#define RTOT (TKN * 2)
#define RPAD (RTOT + NE * 128)
#define NTMAX (RTOT / 128 + NE)

#define NW1 (NE * DH * DM)
#define NW2 (NE * DO * DH)

// dynamic smem layout (per CTA):
//   [0,512)      s_tok (128 int)
//   [512,1024)   s_w   (128 float)
//   [1024, +3*36864)  three stages; each stage = As 128x72 half (18432B) + Bs 128x72 half
#define STAGE_BYTES 36864
#define NSTAGE 3
#define SMEM_BYTES  (1024 + NSTAGE * STAGE_BYTES)

// ---------------- device scratch ----------------
__device__ __half g_xh[TKN * DM];
__device__ __half g_w1h[NE * DH * DM];
__device__ __half g_w2h[NE * DO * DH];
__device__ __half g_h[(size_t)RPAD * DH];
__device__ float  g_y[(size_t)RTOT * DO];
__device__ int    g_bucket[RPAD];
__device__ float  g_bw[RPAD];
__device__ int    g_te[TKN * 2];
__device__ float  g_tw[TKN * 2];
__device__ int    g_counts[NE];
__device__ float  g_psum[NE];
__device__ int    g_fill[NE];
__device__ int    g_tile_e[NTMAX];
__device__ int    g_tile_m[NTMAX];
__device__ int    g_ntiles;

// ---------------- small kernels ----------------
__global__ void k_reset() {
    int i = blockIdx.x * blockDim.x + threadIdx.x;
    if (i < RPAD) g_bucket[i] = -1;
    if (i < NE) { g_counts[i] = 0; g_psum[i] = 0.0f; }
}

__device__ __forceinline__ uint32_t h2_bits(__half2 h) {
    uint32_t u;
    *(__half2*)&u = h;
    return u;
}

// fused w1+w2 fp32->fp16 convert; 8 floats per thread-iter
__global__ void k_convw(const float* __restrict__ w1, const float* __restrict__ w2) {
    const int total = (NW1 + NW2) / 8;
    int t = blockIdx.x * blockDim.x + threadIdx.x;
    int stride = gridDim.x * blockDim.x;
    for (; t < total; t += stride) {
        int i = t * 8;
        const float* s;
        __half* d;
        if (i < NW1) { s = w1 + i; d = g_w1h + i; }
        else         { s = w2 + (i - NW1); d = g_w2h + (i - NW1); }
        float4 v0 = *(const float4*)(s);
        float4 v1 = *(const float4*)(s + 4);
        uint4 o;
        o.x = h2_bits(__floats2half2_rn(v0.x, v0.y));
        o.y = h2_bits(__floats2half2_rn(v0.z, v0.w));
        o.z = h2_bits(__floats2half2_rn(v1.x, v1.y));
        o.w = h2_bits(__floats2half2_rn(v1.z, v1.w));
        *(uint4*)d = o;
    }
}

// one warp per token; float4 loads; ALSO converts the token row to fp16 (g_xh)
__global__ void k_router(const float* __restrict__ x, const float* __restrict__ rw,
                         const float* __restrict__ rb) {
    int warp = (blockIdx.x * blockDim.x + threadIdx.x) >> 5;
    int lane = threadIdx.x & 31;
    if (warp >= TKN) return;
    const float* xr = x + (size_t)warp * DM;
    __half* xhr = g_xh + (size_t)warp * DM;
    float acc[NE];
#pragma unroll
    for (int e = 0; e < NE; e++) acc[e] = 0.0f;
#pragma unroll
    for (int j = 0; j < 8; j++) {
        int i = j * 128 + lane * 4;
        float4 xv = *(const float4*)(xr + i);
        // fused fp16 conversion of x
        uint2 oh;
        oh.x = h2_bits(__floats2half2_rn(xv.x, xv.y));
        oh.y = h2_bits(__floats2half2_rn(xv.z, xv.w));
        *(uint2*)(xhr + i) = oh;
#pragma unroll
        for (int e = 0; e < NE; e++) {
            float4 wv = *(const float4*)(rw + e * DM + i);
            acc[e] += xv.x * wv.x + xv.y * wv.y + xv.z * wv.z + xv.w * wv.w;
        }
    }
#pragma unroll
    for (int off = 16; off; off >>= 1)
#pragma unroll
        for (int e = 0; e < NE; e++) acc[e] += __shfl_xor_sync(0xffffffffu, acc[e], off);

    float lg[NE];
    float mx = -1e30f;
#pragma unroll
    for (int e = 0; e < NE; e++) { lg[e] = acc[e] + rb[e]; mx = fmaxf(mx, lg[e]); }
    float sum = 0.0f;
#pragma unroll
    for (int e = 0; e < NE; e++) { lg[e] = expf(lg[e] - mx); sum += lg[e]; }
    float inv = 1.0f / sum;

    int e0 = 0; float p0 = lg[0];
#pragma unroll
    for (int e = 1; e < NE; e++) if (lg[e] > p0) { p0 = lg[e]; e0 = e; }
    int e1 = -1; float p1 = -1.0f;
#pragma unroll
    for (int e = 0; e < NE; e++) if (e != e0 && lg[e] > p1) { p1 = lg[e]; e1 = e; }
    float wsum = p0 + p1;

    if (lane == 0) {
        g_te[2 * warp] = e0; g_te[2 * warp + 1] = e1;
        g_tw[2 * warp] = p0 / wsum; g_tw[2 * warp + 1] = p1 / wsum;
        atomicAdd(&g_counts[e0], 1);
        atomicAdd(&g_counts[e1], 1);
    }
    if (lane < NE) atomicAdd(&g_psum[lane], lg[lane] * inv);
}

__global__ void k_build() {
    if (threadIdx.x == 0) {
        int off = 0, nt = 0;
        for (int e = 0; e < NE; e++) {
            g_fill[e] = off;
            int c = g_counts[e];
            int tiles = (c + 127) >> 7;
            for (int j = 0; j < tiles; j++) { g_tile_e[nt] = e; g_tile_m[nt] = off + j * 128; nt++; }
            off += tiles * 128;
        }
        g_ntiles = nt;
    }
}

__global__ void k_scatter() {
    int t = blockIdx.x * blockDim.x + threadIdx.x;
    if (t >= TKN) return;
#pragma unroll
    for (int k = 0; k < 2; k++) {
        int e = g_te[2 * t + k];
        int pos = atomicAdd(&g_fill[e], 1);
        g_bucket[pos] = t * 2 + k;
        g_bw[pos] = g_tw[2 * t + k];
    }
}

// ---------------- mma helpers ----------------
__device__ __forceinline__ void ldsm4(uint32_t* r, const void* p) {
    uint32_t addr = (uint32_t)__cvta_generic_to_shared(p);
    asm volatile("ldmatrix.sync.aligned.m8n8.x4.shared.b16 {%0,%1,%2,%3}, [%4];\n"
                 : "=r"(r[0]), "=r"(r[1]), "=r"(r[2]), "=r"(r[3]) : "r"(addr));
}

__device__ __forceinline__ void mma_16816(float* c, const uint32_t* a, const uint32_t* b) {
    asm volatile(
        "mma.sync.aligned.m16n8k16.row.col.f32.f16.f16.f32 "
        "{%0,%1,%2,%3}, {%4,%5,%6,%7}, {%8,%9}, {%0,%1,%2,%3};\n"
        : "+f"(c[0]), "+f"(c[1]), "+f"(c[2]), "+f"(c[3])
        : "r"(a[0]), "r"(a[1]), "r"(a[2]), "r"(a[3]), "r"(b[0]), "r"(b[1]));
}

__device__ __forceinline__ void cpa16(uint32_t dst, const void* src, uint32_t srcsize) {
    asm volatile("cp.async.cg.shared.global [%0], [%1], 16, %2;\n"
                 :: "r"(dst), "l"(src), "r"(srcsize));
}

// ---------------- grouped GEMM: 128x128 tile, BK=64, cp.async 3-stage pipeline -----------
// 8 warps (2x4), warp tile 64x32. Identical to the validated R11/R14 kernel.
template <int KTOT, bool FIRST>
__global__ __launch_bounds__(256, 2) void k_gemm(const float* __restrict__ bias) {
    int t = blockIdx.y;
    if (t >= g_ntiles) return;
    const int e = g_tile_e[t];
    const int mbase = g_tile_m[t];
    const int n0 = blockIdx.x * 128;

    extern __shared__ char sm[];
    int*   s_tok = (int*)sm;
    float* s_w   = (float*)(sm + 512);
    const uint32_t smem_u32 = (uint32_t)__cvta_generic_to_shared(sm);

    const int tid = threadIdx.x;
    const int lane = tid & 31;
    const int wid = tid >> 5;
    const int wm = wid >> 2;   // 0..1
    const int wn = wid & 3;    // 0..3

    if (tid < 128) {
        s_tok[tid] = g_bucket[mbase + tid];
        s_w[tid]   = g_bw[mbase + tid];
    }
    __syncthreads();

    const __half* Bbase =
        (FIRST ? g_w1h + (size_t)e * DH * DM : g_w2h + (size_t)e * DO * DH) + (size_t)n0 * KTOT;

    // loader mapping: thread -> (row tr + 32p, half-col tc), 16B per cp.async
    const int tr = tid >> 3;        // 0..31
    const int tc = (tid & 7) << 3;  // 0..56 step 8 halves

    const __half* aptr[4];
    uint32_t asz[4];
    const __half* bptr[4];
#pragma unroll
    for (int p = 0; p < 4; p++) {
        const int rr = tr + 32 * p;
        if (FIRST) {
            int b = s_tok[rr];
            if (b >= 0) { aptr[p] = g_xh + (size_t)(b >> 1) * DM + tc; asz[p] = 16; }
            else        { aptr[p] = g_xh; asz[p] = 0; }
        } else {
            aptr[p] = g_h + (size_t)(mbase + rr) * DH + tc;
            asz[p] = 16;
        }
        bptr[p] = Bbase + (size_t)rr * KTOT + tc;
    }
    const uint32_t dA = smem_u32 + 1024 + (uint32_t)tr * 144 + (uint32_t)tc * 2;
    const uint32_t dB = dA + 18432;

    auto issue = [&](int chunk, int st) {
        const uint32_t so = (uint32_t)st * STAGE_BYTES;
        const int ko = chunk * 64;
#pragma unroll
        for (int p = 0; p < 4; p++) {
            cpa16(dA + so + p * (32 * 144), aptr[p] + ko, asz[p]);
            cpa16(dB + so + p * (32 * 144), bptr[p] + ko, 16u);
        }
        asm volatile("cp.async.commit_group;" ::: "memory");
    };

    float c[4][4][4];
#pragma unroll
    for (int i = 0; i < 4; i++)
#pragma unroll
        for (int j = 0; j < 4; j++)
#pragma unroll
            for (int q = 0; q < 4; q++) c[i][j][q] = 0.0f;

    constexpr int NC = KTOT / 64;
    issue(0, 0);
    issue(1, 1);
    issue(2, 2);

    int st = 0;
    for (int ch = 0; ch < NC; ch++) {
        const int rem = NC - 1 - ch;
        if (rem >= 2)      asm volatile("cp.async.wait_group 2;" ::: "memory");
        else if (rem == 1) asm volatile("cp.async.wait_group 1;" ::: "memory");
        else               asm volatile("cp.async.wait_group 0;" ::: "memory");
        __syncthreads();

        __half (*As)[72] = (__half(*)[72])(sm + 1024 + st * STAGE_BYTES);
        __half (*Bs)[72] = (__half(*)[72])(sm + 1024 + st * STAGE_BYTES + 18432);

#pragma unroll
        for (int kk = 0; kk < 64; kk += 16) {
            uint32_t a[4][4];
#pragma unroll
            for (int i = 0; i < 4; i++) {
                int row = wm * 64 + i * 16 + (lane & 15);
                int col = kk + ((lane >> 4) << 3);
                ldsm4(a[i], &As[row][col]);
            }
            uint32_t b[4][2];
#pragma unroll
            for (int j2 = 0; j2 < 2; j2++) {
                int q = lane >> 3;
                int row = wn * 32 + j2 * 16 + ((q & 2) ? 8 : 0) + (lane & 7);
                int col = kk + ((q & 1) ? 8 : 0);
                uint32_t r4[4];
                ldsm4(r4, &Bs[row][col]);
                b[2 * j2][0] = r4[0]; b[2 * j2][1] = r4[1];
                b[2 * j2 + 1][0] = r4[2]; b[2 * j2 + 1][1] = r4[3];
            }
#pragma unroll
            for (int i = 0; i < 4; i++)
#pragma unroll
                for (int j = 0; j < 4; j++) mma_16816(c[i][j], a[i], b[j]);
        }
        __syncthreads();
        if (ch + NSTAGE < NC) issue(ch + NSTAGE, st);
        st = (st == NSTAGE - 1) ? 0 : st + 1;
    }

    // epilogue (identical to R1/R11)
    const float* brow = bias + (size_t)e * (FIRST ? DH : DO) + n0;
#pragma unroll
    for (int i = 0; i < 4; i++) {
        int r = wm * 64 + i * 16 + (lane >> 2);
#pragma unroll
        for (int j = 0; j < 4; j++) {
            int cn = wn * 32 + j * 8 + ((lane & 3) << 1);
            float b0 = brow[cn], b1 = brow[cn + 1];
            if (FIRST) {
                float v0 = fmaxf(c[i][j][0] + b0, 0.0f);
                float v1 = fmaxf(c[i][j][1] + b1, 0.0f);
                *(__half2*)(&g_h[(size_t)(mbase + r) * DH + n0 + cn]) = __floats2half2_rn(v0, v1);
                float v2 = fmaxf(c[i][j][2] + b0, 0.0f);
                float v3 = fmaxf(c[i][j][3] + b1, 0.0f);
                *(__half2*)(&g_h[(size_t)(mbase + r + 8) * DH + n0 + cn]) = __floats2half2_rn(v2, v3);
            } else {
                int v = s_tok[r];
                if (v >= 0) {
                    float wgt = s_w[r];
                    float2 o;
                    o.x = wgt * (c[i][j][0] + b0);
                    o.y = wgt * (c[i][j][1] + b1);
                    *(float2*)(&g_y[(size_t)v * DO + n0 + cn]) = o;
                }
                int v2 = s_tok[r + 8];
                if (v2 >= 0) {
                    float wgt = s_w[r + 8];
                    float2 o;
                    o.x = wgt * (c[i][j][2] + b0);
                    o.y = wgt * (c[i][j][3] + b1);
                    *(float2*)(&g_y[(size_t)v2 * DO + n0 + cn]) = o;
                }
            }
        }
    }
}

// float4-vectorized combine over the token-output region
__global__ void k_combine(float* __restrict__ out) {
    int i = (blockIdx.x * blockDim.x + threadIdx.x) * 4;
    if (i >= TKN * DO) return;
    int t = i >> 10;       // DO = 1024
    int cc = i & 1023;
    float4 a = *(const float4*)(&g_y[(size_t)(t * 2) * DO + cc]);
    float4 b = *(const float4*)(&g_y[(size_t)(t * 2 + 1) * DO + cc]);
    float4 o;
    o.x = a.x + b.x; o.y = a.y + b.y; o.z = a.z + b.z; o.w = a.w + b.w;
    *(float4*)(out + i) = o;
}

__global__ void k_final(float* __restrict__ out, int out_size) {
    if (threadIdx.x == 0 && blockIdx.x == 0) {
        for (int i = TKN * DO; i < out_size - 1; i++) out[i] = 0.0f;
        float lb = 0.0f;
        for (int e = 0; e < NE; e++)
            lb += ((float)g_counts[e] / (float)(TKN * 2)) * (g_psum[e] / (float)TKN);
        out[out_size - 1] = 0.01f * (float)NE * lb;
    }
}

// ---------------- launch ----------------
extern "C" void kernel_launch(void* const* d_in, const int* in_sizes, int n_in,
                              void* d_out, int out_size) {
    const float* x  = (const float*)d_in[0];
    const float* rw = (const float*)d_in[1];
    const float* rb = (const float*)d_in[2];
    const float* w1 = (const float*)d_in[3];
    const float* b1 = (const float*)d_in[4];
    const float* w2 = (const float*)d_in[5];
    const float* b2 = (const float*)d_in[6];
    float* out = (float*)d_out;
    (void)in_sizes; (void)n_in;

    cudaFuncSetAttribute(k_gemm<DM, true>,
                         cudaFuncAttributeMaxDynamicSharedMemorySize, SMEM_BYTES);
    cudaFuncSetAttribute(k_gemm<DH, false>,
                         cudaFuncAttributeMaxDynamicSharedMemorySize, SMEM_BYTES);

    k_reset<<<(RPAD + 255) / 256, 256>>>();
    k_convw<<<8192, 256>>>(w1, w2);
    k_router<<<(TKN * 32) / 256, 256>>>(x, rw, rb);   // also produces g_xh
    k_build<<<1, 32>>>();
    k_scatter<<<(TKN + 255) / 256, 256>>>();

    dim3 g1(DH / 128, NTMAX);
    k_gemm<DM, true><<<g1, 256, SMEM_BYTES>>>(b1);
    dim3 g2(DO / 128, NTMAX);
    k_gemm<DH, false><<<g2, 256, SMEM_BYTES>>>(b2);

    k_combine<<<(TKN * DO / 4 + 255) / 256, 256>>>(out);
    k_final<<<1, 32>>>(out, out_size);
}